// round 11
// baseline (speedup 1.0000x reference)
#include <cuda_runtime.h>
#include <cstdint>
#include <cstddef>

// ============================================================================
// W8A8B8O8 Linear, sm_103 base ISA. Hybrid two-engine GEMM, R11 rebalance:
// measured rates: legacy IMMA ~298 MAC/cyc/SM cap (rt55/SMSP), dp4a rt1 on the
// fma pipe => 512 MAC/cyc/SM cap. dp4a becomes the MAJOR engine:
//   - tensor warps (wid 4-7, hi prio): cols [0,48)  warp tile 32x24, 24 accs
//   - dp4a  warps (wid 0-3):           cols [48,128) warp tile 32x40, 40 accs
// BM=64 (shrinks dp4a thread tile to 8x5 -> no spill), BN=128, BK=128,
// 3-stage cp.async, 256 threads, 2 CTAs/SM (72KB smem/CTA).
// x/w arrive as 32-bit promoted int8 -> packed int8 scratch via prep kernel.
// ============================================================================

#define DINLINE __device__ __forceinline__

static constexpr int M_TOTAL = 8192;
static constexpr int K_TOTAL = 4096;
static constexpr int N_TOTAL = 4096;

static constexpr int BM = 64;
static constexpr int BN = 128;
static constexpr int BK = 128;
static constexpr int STAGES = 3;
static constexpr int KCHUNKS = K_TOTAL / BK;      // 32
static constexpr int NUM_M = M_TOTAL / BM;        // 128
static constexpr int NUM_N = N_TOTAL / BN;        // 32
static constexpr int GROUP_M = 8;
static constexpr int NTHREADS = 256;
static constexpr int TENSOR_N = 48;               // tensor cols per CTA tile

static constexpr uint32_t A_BYTES = BM * BK;                  // 8 KB
static constexpr uint32_t B_BYTES = BN * BK;                  // 16 KB
static constexpr uint32_t STAGE_BYTES = A_BYTES + B_BYTES;    // 24 KB
static constexpr uint32_t SMEM_TOTAL = STAGES * STAGE_BYTES;  // 72 KB

// int8 scratch — static __device__ globals, no allocation.
__device__ uint8_t g_x8[(size_t)M_TOTAL * K_TOTAL];   // 32 MB
__device__ uint8_t g_wT[(size_t)N_TOTAL * K_TOTAL];   // 16 MB

// One logical row per 128B smem row; 16B granule xor-swizzled with row low bits.
DINLINE uint32_t swz_addr(uint32_t row, uint32_t gran) {
    return row * 128u + ((gran ^ (row & 7u)) << 4);
}

DINLINE uint32_t smem_u32(const void* p) {
    uint32_t r;
    asm("{ .reg .u64 t; cvta.to.shared.u64 t, %1; cvt.u32.u64 %0, t; }" : "=r"(r) : "l"(p));
    return r;
}

DINLINE void cp_async16(uint32_t saddr, const void* gaddr) {
    asm volatile("cp.async.cg.shared.global [%0], [%1], 16;" :: "r"(saddr), "l"(gaddr) : "memory");
}
DINLINE void cp_commit() { asm volatile("cp.async.commit_group;" ::: "memory"); }
DINLINE void cp_wait1() { asm volatile("cp.async.wait_group 1;" ::: "memory"); }

#define LDSM4(r, addr)                                                         \
    asm volatile("ldmatrix.sync.aligned.m8n8.x4.shared.b16 {%0,%1,%2,%3}, [%4];" \
                 : "=r"((r)[0]), "=r"((r)[1]), "=r"((r)[2]), "=r"((r)[3])      \
                 : "r"(addr))

DINLINE void mma_s8(uint32_t* c, const uint32_t* a, uint32_t b0, uint32_t b1) {
    asm volatile(
        "mma.sync.aligned.m16n8k32.row.col.s32.s8.s8.s32 "
        "{%0,%1,%2,%3}, {%4,%5,%6,%7}, {%8,%9}, {%0,%1,%2,%3};"
        : "+r"(c[0]), "+r"(c[1]), "+r"(c[2]), "+r"(c[3])
        : "r"(a[0]), "r"(a[1]), "r"(a[2]), "r"(a[3]), "r"(b0), "r"(b1));
}

DINLINE int q8(int v, float s) {
    int q = __float2int_rn((float)v * s);   // RNE matches jnp.round
    return q < -128 ? -128 : (q > 127 ? 127 : q);
}

// Auto-detect element storage: small int bit-pattern => int32 storage; else
// interpret the bits as float32 and round-to-nearest-even.
DINLINE uint32_t cvt_b(uint32_t bits) {
    int v = (int)bits;
    if (v < -128 || v > 127) v = __float2int_rn(__int_as_float(bits));
    v = v < -128 ? -128 : (v > 127 ? 127 : v);
    return (uint32_t)v & 0xFFu;
}

// ============================================================================
// Fused prep: blocks [0,8192) convert x -> g_x8; blocks [8192,12288)
// convert+transpose w[K,N] -> g_wT[N,K].
// ============================================================================
__global__ void __launch_bounds__(256) prep_kernel(const uint32_t* __restrict__ xin,
                                                   const uint32_t* __restrict__ w) {
    if (blockIdx.x < 8192) {
        const size_t base = ((size_t)blockIdx.x * 256 + threadIdx.x) * 16;
        alignas(16) uint8_t o[16];
#pragma unroll
        for (int i = 0; i < 16; i += 4) {
            const uint4 v = *reinterpret_cast<const uint4*>(xin + base + i);
            o[i + 0] = (uint8_t)cvt_b(v.x);
            o[i + 1] = (uint8_t)cvt_b(v.y);
            o[i + 2] = (uint8_t)cvt_b(v.z);
            o[i + 3] = (uint8_t)cvt_b(v.w);
        }
        *reinterpret_cast<uint4*>(g_x8 + base) = *reinterpret_cast<const uint4*>(o);
    } else {
        __shared__ uint8_t t[64][65];
        const int bid2 = blockIdx.x - 8192;
        const int tid = threadIdx.x;
        const int n0 = (bid2 & 63) * 64;
        const int k0 = (bid2 >> 6) * 64;

        const int r = tid >> 2;
        const int cseg = (tid & 3) * 16;
        const uint32_t* src = w + (size_t)(k0 + r) * N_TOTAL + n0 + cseg;
#pragma unroll
        for (int i = 0; i < 16; i += 4) {
            const uint4 v = *reinterpret_cast<const uint4*>(src + i);
            t[r][cseg + i + 0] = (uint8_t)cvt_b(v.x);
            t[r][cseg + i + 1] = (uint8_t)cvt_b(v.y);
            t[r][cseg + i + 2] = (uint8_t)cvt_b(v.z);
            t[r][cseg + i + 3] = (uint8_t)cvt_b(v.w);
        }
        __syncthreads();

        const int n = tid >> 2;
        const int kseg = (tid & 3) * 16;
        alignas(16) uint8_t o[16];
#pragma unroll
        for (int j = 0; j < 16; ++j) o[j] = t[kseg + j][n];
        *reinterpret_cast<uint4*>(g_wT + (size_t)(n0 + n) * K_TOTAL + k0 + kseg) =
            *reinterpret_cast<const uint4*>(o);
    }
}

// ============================================================================
// Hybrid GEMM kernel: dp4a-major + tensor-minor, 2 CTAs/SM
// ============================================================================
__global__ void __launch_bounds__(NTHREADS, 2)
w8a8_gemm_kernel(const float* __restrict__ ascale,
                 const float* __restrict__ bscale,
                 float* __restrict__ out) {
    extern __shared__ __align__(1024) uint8_t smem_raw[];
    const uint32_t smem = smem_u32(smem_raw);
    const int t = threadIdx.x;
    const int lane = t & 31;
    const int warp = t >> 5;

    // --- M-grouped raster: W tiles stay L2-resident while A streams ---
    const int bid = blockIdx.x;
    const int group_sz = GROUP_M * NUM_N;          // 256
    const int gid = bid / group_sz;
    const int within = bid - gid * group_sz;
    const int pid_m = gid * GROUP_M + (within % GROUP_M);
    const int pid_n = within / GROUP_M;
    const int m0 = pid_m * BM;
    const int n0 = pid_n * BN;

    // --- producers: A 2 granules + B 4 granules per thread per stage ---
    uint32_t aS[2]; const uint8_t* aG[2];
#pragma unroll
    for (int i = 0; i < 2; ++i) {
        const int q = t + i * NTHREADS;            // 0..511
        const int m = q >> 3, g = q & 7;
        aS[i] = smem + swz_addr((uint32_t)m, (uint32_t)g);
        aG[i] = g_x8 + (size_t)(m0 + m) * K_TOTAL + g * 16;
    }
    uint32_t bS[4]; const uint8_t* bG[4];
#pragma unroll
    for (int i = 0; i < 4; ++i) {
        const int q = t + i * NTHREADS;            // 0..1023
        const int n = q >> 3, g = q & 7;
        bS[i] = smem + A_BYTES + swz_addr((uint32_t)n, (uint32_t)g);
        bG[i] = g_wT + (size_t)(n0 + n) * K_TOTAL + g * 16;
    }

    auto load_stage = [&](int s, int chunk) {
        const uint32_t so = s * STAGE_BYTES;
        const size_t ko = (size_t)chunk * BK;
#pragma unroll
        for (int i = 0; i < 2; ++i) cp_async16(aS[i] + so, aG[i] + ko);
#pragma unroll
        for (int i = 0; i < 4; ++i) cp_async16(bS[i] + so, bG[i] + ko);
    };

    const float scl = ascale[0] * bscale[0];

    // --- prologue: stages 0,1 ---
#pragma unroll
    for (int s = 0; s < STAGES - 1; ++s) { load_stage(s, s); cp_commit(); }

    if (warp >= 4) {
        // ====== tensor engine (minor, hi-wid priority): cols [0, 48) ======
        const int tw = warp - 4;
        const int wm = tw >> 1;     // 0..1 (32-row band)
        const int wn = tw & 1;      // 0..1 (24-col band)

        // A x4 (PTX ISA a0..a3): m0=r0-7 klo, m1=r8-15 klo, m2=r0-7 khi, m3=r8-15 khi
        uint32_t aOff, bOff;
        {
            const int mlocal = ((lane >> 3) & 1) * 8 + (lane & 7);
            const int k16a = lane >> 4;
            const int am = wm * 32 + mlocal;
            aOff = swz_addr((uint32_t)am, (uint32_t)k16a);
            const int j = lane >> 3;
            const int nlocal = (j >> 1) * 8 + (lane & 7);
            const int k16b = j & 1;
            const int bn = wn * 24 + nlocal;
            bOff = A_BYTES + swz_addr((uint32_t)bn, (uint32_t)k16b);
        }

        uint32_t acc[2][3][4];
#pragma unroll
        for (int mt = 0; mt < 2; ++mt)
#pragma unroll
            for (int nt = 0; nt < 3; ++nt)
#pragma unroll
                for (int r = 0; r < 4; ++r) acc[mt][nt][r] = 0;

        for (int c = 0; c < KCHUNKS; ++c) {
            cp_wait1();
            __syncthreads();
            if (c + STAGES - 1 < KCHUNKS)
                load_stage((c + STAGES - 1) % STAGES, c + STAGES - 1);
            cp_commit();

            const uint32_t so = (uint32_t)(c % STAGES) * STAGE_BYTES;
#pragma unroll
            for (int kp = 0; kp < 4; ++kp) {
                const uint32_t kx = (uint32_t)kp << 5;
                uint32_t av[2][4];
#pragma unroll
                for (int mt = 0; mt < 2; ++mt) {
                    const uint32_t ad = smem + ((aOff + so + mt * 2048u) ^ kx);
                    LDSM4(av[mt], ad);
                }
                uint32_t bv[2][4];
#pragma unroll
                for (int nt2 = 0; nt2 < 2; ++nt2) {
                    const uint32_t bd = smem + ((bOff + so + nt2 * 2048u) ^ kx);
                    LDSM4(bv[nt2], bd);
                }
#pragma unroll
                for (int mt = 0; mt < 2; ++mt)
#pragma unroll
                    for (int nt = 0; nt < 3; ++nt) {
                        const uint32_t* bp = &bv[nt >> 1][(nt & 1) * 2];
                        mma_s8(acc[mt][nt], av[mt], bp[0], bp[1]);
                    }
            }
        }

        // epilogue (tensor)
#pragma unroll
        for (int mt = 0; mt < 2; ++mt) {
#pragma unroll
            for (int nt = 0; nt < 3; ++nt) {
                const int row = m0 + wm * 32 + mt * 16 + (lane >> 2);
                const int col = n0 + wn * 24 + nt * 8 + 2 * (lane & 3);
                const int* a4 = reinterpret_cast<const int*>(acc[mt][nt]);
                float2 v0, v1;
                v0.x = (float)q8(a4[0], scl);
                v0.y = (float)q8(a4[1], scl);
                v1.x = (float)q8(a4[2], scl);
                v1.y = (float)q8(a4[3], scl);
                *reinterpret_cast<float2*>(out + (size_t)row * N_TOTAL + col) = v0;
                *reinterpret_cast<float2*>(out + (size_t)(row + 8) * N_TOTAL + col) = v1;
            }
        }
    } else {
        // ====== dp4a engine (major): cols [48, 128), warp tile 32x40 ======
        const int r0 = (warp & 1) * 32;             // row band
        const int c0 = TENSOR_N + (warp >> 1) * 40; // col band
        const int tr = lane >> 3;                   // 0..3 -> 8-row group
        const int tc = lane & 7;                    // 0..7 -> 5-col group

        uint32_t abase[8], bbase[5];
        uint32_t as7[8], bs7[5];
#pragma unroll
        for (int i = 0; i < 8; ++i) {
            const int r = r0 + tr * 8 + i;
            abase[i] = (uint32_t)r * 128u;
            as7[i] = (uint32_t)r & 7u;
        }
#pragma unroll
        for (int j = 0; j < 5; ++j) {
            const int n = c0 + tc * 5 + j;
            bbase[j] = A_BYTES + (uint32_t)n * 128u;
            bs7[j] = (uint32_t)n & 7u;
        }

        int accd[8][5];
#pragma unroll
        for (int i = 0; i < 8; ++i)
#pragma unroll
            for (int j = 0; j < 5; ++j) accd[i][j] = 0;

        for (int c = 0; c < KCHUNKS; ++c) {
            cp_wait1();
            __syncthreads();
            if (c + STAGES - 1 < KCHUNKS)
                load_stage((c + STAGES - 1) % STAGES, c + STAGES - 1);
            cp_commit();

            const uint32_t so = (uint32_t)(c % STAGES) * STAGE_BYTES;
#pragma unroll
            for (int g = 0; g < 8; ++g) {   // 8 x 16B k-granules
                uint4 br[5];
#pragma unroll
                for (int j = 0; j < 5; ++j)
                    br[j] = *reinterpret_cast<const uint4*>(
                        smem_raw + so + bbase[j] + ((((uint32_t)g ^ bs7[j])) << 4));
#pragma unroll
                for (int ih = 0; ih < 2; ++ih) {
                    uint4 ar[4];
#pragma unroll
                    for (int ii = 0; ii < 4; ++ii) {
                        const int i = ih * 4 + ii;
                        ar[ii] = *reinterpret_cast<const uint4*>(
                            smem_raw + so + abase[i] + ((((uint32_t)g ^ as7[i])) << 4));
                    }
#pragma unroll
                    for (int ii = 0; ii < 4; ++ii)
#pragma unroll
                        for (int j = 0; j < 5; ++j) {
                            int& a = accd[ih * 4 + ii][j];
                            a = __dp4a((int)ar[ii].x, (int)br[j].x, a);
                            a = __dp4a((int)ar[ii].y, (int)br[j].y, a);
                            a = __dp4a((int)ar[ii].z, (int)br[j].z, a);
                            a = __dp4a((int)ar[ii].w, (int)br[j].w, a);
                        }
                }
            }
        }

        // epilogue (dp4a) — scalar stores (5 cols, odd alignment)
#pragma unroll
        for (int i = 0; i < 8; ++i) {
            const int row = m0 + r0 + tr * 8 + i;
            float* orow = out + (size_t)row * N_TOTAL + n0 + c0 + tc * 5;
#pragma unroll
            for (int j = 0; j < 5; ++j)
                orow[j] = (float)q8(accd[i][j], scl);
        }
    }
}

// ============================================================================
// Launch — identify inputs by element count (robust to metadata ordering)
// ============================================================================
extern "C" void kernel_launch(void* const* d_in, const int* in_sizes, int n_in,
                              void* d_out, int out_size) {
    (void)out_size;
    const uint32_t* x = nullptr;
    const uint32_t* w = nullptr;
    const float* s1 = nullptr;
    const float* s2 = nullptr;
    for (int i = 0; i < n_in; ++i) {
        const long sz = in_sizes[i];
        if (sz == (long)M_TOTAL * K_TOTAL) x = (const uint32_t*)d_in[i];
        else if (sz == (long)K_TOTAL * N_TOTAL) w = (const uint32_t*)d_in[i];
        else if (sz == 1) { if (!s1) s1 = (const float*)d_in[i]; else s2 = (const float*)d_in[i]; }
    }
    if (!x || !w || !s1 || !s2) return;

    cudaFuncSetAttribute(w8a8_gemm_kernel,
                         cudaFuncAttributeMaxDynamicSharedMemorySize, (int)SMEM_TOTAL);

    prep_kernel<<<8192 + 4096, 256>>>(x, w);
    w8a8_gemm_kernel<<<NUM_M * NUM_N, NTHREADS, SMEM_TOTAL>>>(s1, s2, (float*)d_out);
}